// round 6
// baseline (speedup 1.0000x reference)
#include <cuda_runtime.h>

#define BATCH 128
#define CH 1024

// Table config
#define G 64
#define GRANGE 6.0f
#define GSTEP (2.0f * GRANGE / (G - 1))

// GEMM config
#define G_NTILE 64
#define G_KSPLIT 8
#define G_KCHUNK (CH / G_KSPLIT)   // 128
#define KT 32
#define SROW 34                    // row stride (floats): conflict-free LDS.64
#define NTILES (CH / G_NTILE)      // 16

// Scratch (allocation-free rule: __device__ globals)
static __device__ float g_h[BATCH * CH];     // 512 KB: h = visual + crossed
static __device__ float g_acc[BATCH * CH];   // 512 KB: GEMM accumulator (atomic)
static __device__ unsigned int g_cnt[NTILES];

typedef unsigned long long u64;
typedef unsigned int u32;

__device__ __forceinline__ float ex2f(float x) {
    float y;
    asm("ex2.approx.ftz.f32 %0, %1;" : "=f"(y) : "f"(x));
    return y;
}
__device__ __forceinline__ u64 fma2(u64 a, u64 b, u64 c) {
    u64 r; asm("fma.rn.f32x2 %0, %1, %2, %3;" : "=l"(r) : "l"(a), "l"(b), "l"(c)); return r;
}
__device__ __forceinline__ void upkf(float& lo, float& hi, u64 v) {
    asm("mov.b64 {%0,%1}, %2;" : "=f"(lo), "=f"(hi) : "l"(v));
}

// ---------------------------------------------------------------------------
// Kernel 1: fused table + Hermite interp.  One CTA per batch, 256 threads.
// Phase 1: G grid points of g(s) = sum_j e^{s v_j} v_j / sum_j e^{s v_j} and
//          g'(s) = M2/D - g^2, computed 4-threads-per-point (CH split 4 ways,
//          interleaved float4 stride so smem reads are conflict-free).
// Phase 2: cubic Hermite interp at t_i -> h = v_i + g(t_i); zero g_acc slice.
// Also zeroes the finalize counters (CTA 0).
// ---------------------------------------------------------------------------
__global__ __launch_bounds__(256) void fused_cross(
    const float* __restrict__ visual, const float* __restrict__ tactile)
{
    __shared__ __align__(16) float vl[CH];    // v * log2e
    __shared__ __align__(16) float vl2[CH];   // (v * log2e)^2
    __shared__ float sden[G][4], snum[G][4], sm2[G][4];
    __shared__ float tab[G], der[G];

    const int b = blockIdx.x;
    const float LOG2E = 1.4426950408889634f;
    const float LN2   = 0.6931471805599453f;

    if (b == 0 && threadIdx.x < NTILES) g_cnt[threadIdx.x] = 0;

    const float* vb = visual + b * CH;
#pragma unroll
    for (int k = 0; k < 4; k++) {
        int idx = threadIdx.x + k * 256;
        float v = vb[idx] * LOG2E;
        vl[idx] = v;
        vl2[idx] = v * v;
    }
    __syncthreads();

    // ---- Phase 1: table ----
    const int p  = threadIdx.x >> 2;   // grid point
    const int h4 = threadIdx.x & 3;    // quarter of CH
    const float s = -GRANGE + GSTEP * (float)p;

    float den0 = 0.f, den1 = 0.f;
    float num0 = 0.f, num1 = 0.f;
    float m20 = 0.f, m21 = 0.f;
    const float4* v4 = reinterpret_cast<const float4*>(vl);
    const float4* w4 = reinterpret_cast<const float4*>(vl2);
#pragma unroll 4
    for (int j = 0; j < CH / 16; j++) {
        float4 v = v4[j * 4 + h4];
        float4 w = w4[j * 4 + h4];
        float e0 = ex2f(s * v.x);
        float e1 = ex2f(s * v.y);
        float e2 = ex2f(s * v.z);
        float e3 = ex2f(s * v.w);
        den0 += e0 + e2;
        den1 += e1 + e3;
        num0 = fmaf(e0, v.x, num0);
        num1 = fmaf(e1, v.y, num1);
        num0 = fmaf(e2, v.z, num0);
        num1 = fmaf(e3, v.w, num1);
        m20 = fmaf(e0, w.x, m20);
        m21 = fmaf(e1, w.y, m21);
        m20 = fmaf(e2, w.z, m20);
        m21 = fmaf(e3, w.w, m21);
    }
    sden[p][h4] = den0 + den1;
    snum[p][h4] = num0 + num1;
    sm2[p][h4]  = m20 + m21;
    __syncthreads();

    if (threadIdx.x < G) {
        int q = threadIdx.x;
        float den = (sden[q][0] + sden[q][1]) + (sden[q][2] + sden[q][3]);
        float num = (snum[q][0] + snum[q][1]) + (snum[q][2] + snum[q][3]);
        float m2  = (sm2[q][0] + sm2[q][1]) + (sm2[q][2] + sm2[q][3]);
        float inv = __fdividef(1.0f, den);
        float nd = num * inv;                          // = log2e * g
        tab[q] = nd * LN2;                             // crossed value
        der[q] = (LN2 * LN2) * (m2 * inv - nd * nd) * GSTEP; // dg/du (grid units)
    }
    __syncthreads();

    // ---- Phase 2: interp + zero g_acc ----
#pragma unroll
    for (int k = 0; k < 4; k++) {
        int i = threadIdx.x + k * 256;
        float t = tactile[b * CH + i];

        float x = (t + GRANGE) * (1.0f / GSTEP);
        x = fminf(fmaxf(x, 0.0f), (float)(G - 1) - 1e-3f);
        int i1 = (int)x;
        float u = x - (float)i1;
        float p1 = tab[i1], p2 = tab[i1 + 1];
        float m1 = der[i1], m2 = der[i1 + 1];
        float c2 = 3.0f * (p2 - p1) - 2.0f * m1 - m2;
        float c3 = 2.0f * (p1 - p2) + m1 + m2;
        float crossed = ((c3 * u + c2) * u + m1) * u + p1;

        g_h[b * CH + i] = vl[i] * LN2 + crossed;   // vl*ln2 = v_i
        g_acc[b * CH + i] = 0.f;
    }
}

// ---------------------------------------------------------------------------
// Kernel 2: split-K GEMM (k-packed f32x2 FFMA) + in-kernel finalize.
// y[b,o] = sum_k Wc[o,k] h[b,k];  Wc = center tap of 3x3 conv (stride-9 gather).
// grid = 16 n-tiles x 8 k-splits = 128 CTAs, 128 threads, 8b x 8o per thread.
// Partials atomically accumulated into g_acc; the LAST k-split CTA per n-tile
// (per-tile counter) applies bias + BN + LeakyReLU and writes d_out.
// ---------------------------------------------------------------------------
__global__ __launch_bounds__(128) void gemm_final(
    const float* __restrict__ conv_w,
    const float* __restrict__ cb, const float* __restrict__ gamma,
    const float* __restrict__ beta, const float* __restrict__ mean,
    const float* __restrict__ var, float* __restrict__ out)
{
    __shared__ __align__(16) float sh[BATCH][SROW];    // 128 x 34 floats
    __shared__ __align__(16) float sw[G_NTILE][SROW];  // 64 x 34 floats
    __shared__ float sA[G_NTILE], sC[G_NTILE];
    __shared__ int s_done;

    const int nb = blockIdx.x & (NTILES - 1);
    const int kz = blockIdx.x >> 4;
    const int nbase = nb * G_NTILE;
    const int kbase = kz * G_KCHUNK;

    const int tx = threadIdx.x & 7;    // o lane (8 groups of 8)
    const int ty = threadIdx.x >> 3;   // b lane (16 groups of 8)

    u64 acc[8][8] = {};

    for (int kk = 0; kk < G_KCHUNK; kk += KT) {
        if (kk) __syncthreads();
        // stage h: 128 x 32 floats (coalesced float4)
#pragma unroll
        for (int it = 0; it < 8; it++) {
            int l = threadIdx.x + it * 128;
            int r = l >> 3, c = (l & 7) * 4;
            float4 hv = *(const float4*)&g_h[r * CH + kbase + kk + c];
            sh[r][c] = hv.x; sh[r][c + 1] = hv.y; sh[r][c + 2] = hv.z; sh[r][c + 3] = hv.w;
        }
        // stage w: 64 x 32 center taps (stride-9 gather)
#pragma unroll
        for (int it = 0; it < 16; it++) {
            int l = threadIdx.x + it * 128;
            int o = l >> 5, c = l & 31;
            sw[o][c] = conv_w[((nbase + o) * CH + (kbase + kk + c)) * 9 + 4];
        }
        __syncthreads();

#pragma unroll
        for (int kp = 0; kp < KT / 2; kp++) {
            u64 hb[8], wo[8];
#pragma unroll
            for (int bi = 0; bi < 8; bi++)
                hb[bi] = *(const u64*)&sh[ty + 16 * bi][kp * 2];
#pragma unroll
            for (int oi = 0; oi < 8; oi++)
                wo[oi] = *(const u64*)&sw[tx + 8 * oi][kp * 2];
#pragma unroll
            for (int bi = 0; bi < 8; bi++)
#pragma unroll
                for (int oi = 0; oi < 8; oi++)
                    acc[bi][oi] = fma2(hb[bi], wo[oi], acc[bi][oi]);
        }
    }

    // partial accumulate
#pragma unroll
    for (int bi = 0; bi < 8; bi++) {
        int b = ty + 16 * bi;
#pragma unroll
        for (int oi = 0; oi < 8; oi++) {
            float lo, hi; upkf(lo, hi, acc[bi][oi]);
            atomicAdd(&g_acc[b * CH + nbase + tx + 8 * oi], lo + hi);
        }
    }

    // -------- finalize: last k-split CTA for this n-tile applies epilogue ----
    __threadfence();            // make our atomics globally visible
    __syncthreads();            // all threads' atomics issued before count
    if (threadIdx.x == 0) {
        unsigned int old = atomicAdd(&g_cnt[nb], 1u);
        s_done = (old == G_KSPLIT - 1) ? 1 : 0;
    }
    __syncthreads();
    if (!s_done) return;

    __threadfence();            // acquire: see all other CTAs' g_acc atomics
    if (threadIdx.x < G_NTILE) {
        int o = nbase + threadIdx.x;
        float A = gamma[o] * rsqrtf(var[o] + 1e-5f);
        sA[threadIdx.x] = A;
        sC[threadIdx.x] = (cb[o] - mean[o]) * A + beta[o];
    }
    __syncthreads();

    // 128 b x 64 o = 2048 float4 groups; 16 per thread
    for (int e = threadIdx.x; e < BATCH * G_NTILE / 4; e += 128) {
        int b = e >> 4;
        int oq = (e & 15) * 4;
        int off = b * CH + nbase + oq;
        float4 sv = __ldcg((const float4*)&g_acc[off]);
        float4 r;
        float v;
        v = sv.x * sA[oq + 0] + sC[oq + 0]; r.x = v > 0.f ? v : 0.1f * v;
        v = sv.y * sA[oq + 1] + sC[oq + 1]; r.y = v > 0.f ? v : 0.1f * v;
        v = sv.z * sA[oq + 2] + sC[oq + 2]; r.z = v > 0.f ? v : 0.1f * v;
        v = sv.w * sA[oq + 3] + sC[oq + 3]; r.w = v > 0.f ? v : 0.1f * v;
        *(float4*)&out[off] = r;
    }
}

extern "C" void kernel_launch(void* const* d_in, const int* in_sizes, int n_in,
                              void* d_out, int out_size)
{
    const float* visual  = (const float*)d_in[0];
    const float* tactile = (const float*)d_in[1];
    const float* conv_w  = (const float*)d_in[2];
    const float* conv_b  = (const float*)d_in[3];
    const float* gamma   = (const float*)d_in[4];
    const float* beta    = (const float*)d_in[5];
    const float* mean    = (const float*)d_in[6];
    const float* var     = (const float*)d_in[7];
    float* out = (float*)d_out;

    fused_cross<<<BATCH, 256>>>(visual, tactile);
    gemm_final<<<NTILES * G_KSPLIT, 128>>>(conv_w, conv_b, gamma, beta, mean, var, out);
}

// round 7
// speedup vs baseline: 1.2231x; 1.2231x over previous
#include <cuda_runtime.h>

#define BATCH 128
#define CH 1024

// Table config
#define G 32
#define GRANGE 6.0f
#define GSTEP (2.0f * GRANGE / (G - 1))

// GEMM config
#define G_NTILE 64
#define G_KSPLIT 16
#define G_KCHUNK (CH / G_KSPLIT)   // 64
#define KT 32
#define NTILES (CH / G_NTILE)      // 16
#define SHROW 36                   // h-tile row stride (floats), 144B = 16*9
#define SWROW 132                  // w-tile row stride (floats), 528B = 16*33

// Scratch (allocation-free rule: __device__ globals)
static __device__ float g_h[BATCH * CH];     // 512 KB: h = visual + crossed
static __device__ float g_acc[BATCH * CH];   // 512 KB: GEMM accumulator (atomic)
static __device__ unsigned int g_cnt[NTILES];

typedef unsigned long long u64;
typedef unsigned int u32;

__device__ __forceinline__ float ex2f(float x) {
    float y;
    asm("ex2.approx.ftz.f32 %0, %1;" : "=f"(y) : "f"(x));
    return y;
}
__device__ __forceinline__ u64 fma2(u64 a, u64 b, u64 c) {
    u64 r; asm("fma.rn.f32x2 %0, %1, %2, %3;" : "=l"(r) : "l"(a), "l"(b), "l"(c)); return r;
}
__device__ __forceinline__ void upkf(float& lo, float& hi, u64 v) {
    asm("mov.b64 {%0,%1}, %2;" : "=f"(lo), "=f"(hi) : "l"(v));
}

// ---------------------------------------------------------------------------
// Kernel 1: fused table + Hermite interp.  One CTA per batch, 256 threads.
// Phase 1: G=32 grid points of g(s)=sum_j e^{s v_j}v_j / sum_j e^{s v_j} and
//          g'(s)=M2/D-g^2, 8 threads per point (CH split 8 ways, interleaved).
// Phase 2: cubic Hermite interp at t_i -> h = v_i + g(t_i); zero g_acc slice.
// CTA 0 also zeroes the finalize counters.
// ---------------------------------------------------------------------------
__global__ __launch_bounds__(256) void fused_cross(
    const float* __restrict__ visual, const float* __restrict__ tactile)
{
    __shared__ __align__(16) float vl[CH];    // v * log2e
    __shared__ __align__(16) float vl2[CH];   // (v * log2e)^2
    __shared__ float sden[G][8], snum[G][8], sm2[G][8];
    __shared__ float tab[G], der[G];

    const int b = blockIdx.x;
    const float LOG2E = 1.4426950408889634f;
    const float LN2   = 0.6931471805599453f;

    if (b == 0 && threadIdx.x < NTILES) g_cnt[threadIdx.x] = 0;

    const float* vb = visual + b * CH;
#pragma unroll
    for (int k = 0; k < 4; k++) {
        int idx = threadIdx.x + k * 256;
        float v = vb[idx] * LOG2E;
        vl[idx] = v;
        vl2[idx] = v * v;
    }
    __syncthreads();

    // ---- Phase 1: table (8 threads per grid point) ----
    const int p  = threadIdx.x >> 3;   // grid point 0..31
    const int h8 = threadIdx.x & 7;    // eighth of CH
    const float s = -GRANGE + GSTEP * (float)p;

    float den0 = 0.f, den1 = 0.f;
    float num0 = 0.f, num1 = 0.f;
    float m20 = 0.f, m21 = 0.f;
    const float4* v4 = reinterpret_cast<const float4*>(vl);
    const float4* w4 = reinterpret_cast<const float4*>(vl2);
#pragma unroll 4
    for (int j = 0; j < CH / 32; j++) {
        float4 v = v4[j * 8 + h8];
        float4 w = w4[j * 8 + h8];
        float e0 = ex2f(s * v.x);
        float e1 = ex2f(s * v.y);
        float e2 = ex2f(s * v.z);
        float e3 = ex2f(s * v.w);
        den0 += e0 + e2;
        den1 += e1 + e3;
        num0 = fmaf(e0, v.x, num0);
        num1 = fmaf(e1, v.y, num1);
        num0 = fmaf(e2, v.z, num0);
        num1 = fmaf(e3, v.w, num1);
        m20 = fmaf(e0, w.x, m20);
        m21 = fmaf(e1, w.y, m21);
        m20 = fmaf(e2, w.z, m20);
        m21 = fmaf(e3, w.w, m21);
    }
    sden[p][h8] = den0 + den1;
    snum[p][h8] = num0 + num1;
    sm2[p][h8]  = m20 + m21;
    __syncthreads();

    if (threadIdx.x < G) {
        int q = threadIdx.x;
        float den = 0.f, num = 0.f, m2 = 0.f;
#pragma unroll
        for (int r = 0; r < 8; r++) {
            den += sden[q][r]; num += snum[q][r]; m2 += sm2[q][r];
        }
        float inv = __fdividef(1.0f, den);
        float nd = num * inv;                          // = log2e * g
        tab[q] = nd * LN2;                             // crossed value
        der[q] = (LN2 * LN2) * (m2 * inv - nd * nd) * GSTEP; // dg/du (grid units)
    }
    __syncthreads();

    // ---- Phase 2: interp + zero g_acc ----
#pragma unroll
    for (int k = 0; k < 4; k++) {
        int i = threadIdx.x + k * 256;
        float t = tactile[b * CH + i];

        float x = (t + GRANGE) * (1.0f / GSTEP);
        x = fminf(fmaxf(x, 0.0f), (float)(G - 1) - 1e-3f);
        int i1 = (int)x;
        float u = x - (float)i1;
        float p1 = tab[i1], p2 = tab[i1 + 1];
        float m1 = der[i1], m2 = der[i1 + 1];
        float c2 = 3.0f * (p2 - p1) - 2.0f * m1 - m2;
        float c3 = 2.0f * (p1 - p2) + m1 + m2;
        float crossed = ((c3 * u + c2) * u + m1) * u + p1;

        g_h[b * CH + i] = vl[i] * LN2 + crossed;   // vl*ln2 = v_i
        g_acc[b * CH + i] = 0.f;
    }
}

// ---------------------------------------------------------------------------
// Kernel 2: split-K GEMM (k-packed f32x2 FFMA) + in-kernel finalize.
// grid = 16 n-tiles x 16 k-splits = 256 CTAs, 256 threads, 2 CTAs/SM.
// CTA tile 128b x 64o, K chunk 64 (two KT=32 stages). Per-thread 8b x 4o.
// W tile stored k-major packed ([kp][2o]) -> conflict-free LDS.64 in compute.
// Partials via atomicAdd; last k-split CTA per n-tile applies bias+BN+LeakyReLU.
// ---------------------------------------------------------------------------
__global__ __launch_bounds__(256, 2) void gemm_final(
    const float* __restrict__ conv_w,
    const float* __restrict__ cb, const float* __restrict__ gamma,
    const float* __restrict__ beta, const float* __restrict__ mean,
    const float* __restrict__ var, float* __restrict__ out)
{
    __shared__ __align__(16) float sh[BATCH * SHROW];   // 18.4 KB  [b][k]
    __shared__ __align__(16) float sw[(KT / 2) * SWROW]; // 8.4 KB  [kp][2o+par]
    __shared__ float sA[G_NTILE], sC[G_NTILE];
    __shared__ int s_done;

    const int nb = blockIdx.x & (NTILES - 1);
    const int kz = blockIdx.x >> 4;
    const int nbase = nb * G_NTILE;
    const int kbase = kz * G_KCHUNK;

    const int tx = threadIdx.x & 15;   // o group: o = tx + 16*oi, oi<4
    const int ty = threadIdx.x >> 4;   // b group: b = ty + 16*bi, bi<8

    u64 acc[8][4] = {};

    for (int kk = 0; kk < G_KCHUNK; kk += KT) {
        if (kk) __syncthreads();
        // stage h: 128 b x 32 k floats (coalesced float4 loads)
#pragma unroll
        for (int it = 0; it < 4; it++) {
            int e = threadIdx.x + it * 256;
            int r = e >> 3, c4 = (e & 7) * 4;
            float4 hv = *(const float4*)&g_h[r * CH + kbase + kk + c4];
            *(float4*)&sh[r * SHROW + c4] = hv;
        }
        // stage w: 64 o x 32 k center taps (stride-9 gather), k-major packed
#pragma unroll
        for (int it = 0; it < 8; it++) {
            int e = threadIdx.x + it * 256;
            int o = e & 63, c = e >> 6;          // c in 0..31
            sw[(c >> 1) * SWROW + 2 * o + (c & 1)] =
                conv_w[((nbase + o) * CH + (kbase + kk + c)) * 9 + 4];
        }
        __syncthreads();

#pragma unroll
        for (int kp = 0; kp < KT / 2; kp++) {
            u64 hb[8], wo[4];
#pragma unroll
            for (int bi = 0; bi < 8; bi++)
                hb[bi] = *(const u64*)&sh[(ty + 16 * bi) * SHROW + kp * 2];
#pragma unroll
            for (int oi = 0; oi < 4; oi++)
                wo[oi] = *(const u64*)&sw[kp * SWROW + 2 * (tx + 16 * oi)];
#pragma unroll
            for (int bi = 0; bi < 8; bi++)
#pragma unroll
                for (int oi = 0; oi < 4; oi++)
                    acc[bi][oi] = fma2(hb[bi], wo[oi], acc[bi][oi]);
        }
    }

    // partial accumulate (REDG, spread addresses)
#pragma unroll
    for (int bi = 0; bi < 8; bi++) {
        int b = ty + 16 * bi;
#pragma unroll
        for (int oi = 0; oi < 4; oi++) {
            float lo, hi; upkf(lo, hi, acc[bi][oi]);
            atomicAdd(&g_acc[b * CH + nbase + tx + 16 * oi], lo + hi);
        }
    }

    // -------- finalize: last k-split CTA for this n-tile applies epilogue ----
    __threadfence();            // make our atomics globally visible
    __syncthreads();            // all threads' atomics issued before count
    if (threadIdx.x == 0) {
        unsigned int old = atomicAdd(&g_cnt[nb], 1u);
        s_done = (old == G_KSPLIT - 1) ? 1 : 0;
    }
    __syncthreads();
    if (!s_done) return;

    __threadfence();            // acquire: see all other CTAs' g_acc atomics
    if (threadIdx.x < G_NTILE) {
        int o = nbase + threadIdx.x;
        float A = gamma[o] * rsqrtf(var[o] + 1e-5f);
        sA[threadIdx.x] = A;
        sC[threadIdx.x] = (cb[o] - mean[o]) * A + beta[o];
    }
    __syncthreads();

    // 128 b x 64 o = 2048 float4 groups; 8 per thread
#pragma unroll
    for (int it = 0; it < 8; it++) {
        int e = threadIdx.x + it * 256;
        int b = e >> 4;
        int oq = (e & 15) * 4;
        int off = b * CH + nbase + oq;
        float4 sv = __ldcg((const float4*)&g_acc[off]);
        float4 r;
        float v;
        v = sv.x * sA[oq + 0] + sC[oq + 0]; r.x = v > 0.f ? v : 0.1f * v;
        v = sv.y * sA[oq + 1] + sC[oq + 1]; r.y = v > 0.f ? v : 0.1f * v;
        v = sv.z * sA[oq + 2] + sC[oq + 2]; r.z = v > 0.f ? v : 0.1f * v;
        v = sv.w * sA[oq + 3] + sC[oq + 3]; r.w = v > 0.f ? v : 0.1f * v;
        *(float4*)&out[off] = r;
    }
}

extern "C" void kernel_launch(void* const* d_in, const int* in_sizes, int n_in,
                              void* d_out, int out_size)
{
    const float* visual  = (const float*)d_in[0];
    const float* tactile = (const float*)d_in[1];
    const float* conv_w  = (const float*)d_in[2];
    const float* conv_b  = (const float*)d_in[3];
    const float* gamma   = (const float*)d_in[4];
    const float* beta    = (const float*)d_in[5];
    const float* mean    = (const float*)d_in[6];
    const float* var     = (const float*)d_in[7];
    float* out = (float*)d_out;

    fused_cross<<<BATCH, 256>>>(visual, tactile);
    gemm_final<<<NTILES * G_KSPLIT, 256>>>(conv_w, conv_b, gamma, beta, mean, var, out);
}

// round 8
// speedup vs baseline: 1.3849x; 1.1323x over previous
#include <cuda_runtime.h>

#define BATCH 128
#define CH 1024

// Table config
#define G 32
#define GRANGE 6.0f
#define GSTEP (2.0f * GRANGE / (G - 1))

// GEMM config
#define G_NTILE 64
#define G_KSPLIT 16
#define G_KCHUNK (CH / G_KSPLIT)   // 64
#define KT 32
#define NTILES (CH / G_NTILE)      // 16
#define SHROW 36                   // h row stride (floats): 144B, 16B-aligned
#define SWROW 34                   // w row stride (floats): u64-aligned, bank-rotated

// Scratch (allocation-free rule: __device__ globals)
static __device__ float g_h[BATCH * CH];     // 512 KB
static __device__ float g_acc[BATCH * CH];   // 512 KB
static __device__ unsigned int g_cnt[NTILES];

typedef unsigned long long u64;
typedef unsigned int u32;

__device__ __forceinline__ float ex2f(float x) {
    float y;
    asm("ex2.approx.ftz.f32 %0, %1;" : "=f"(y) : "f"(x));
    return y;
}
__device__ __forceinline__ u64 fma2(u64 a, u64 b, u64 c) {
    u64 r; asm("fma.rn.f32x2 %0, %1, %2, %3;" : "=l"(r) : "l"(a), "l"(b), "l"(c)); return r;
}
__device__ __forceinline__ void upkf(float& lo, float& hi, u64 v) {
    asm("mov.b64 {%0,%1}, %2;" : "=f"(lo), "=f"(hi) : "l"(v));
}
__device__ __forceinline__ void cpa4(u32 dst, const float* src) {
    asm volatile("cp.async.ca.shared.global [%0], [%1], 4;" :: "r"(dst), "l"(src));
}
__device__ __forceinline__ void cpa16(u32 dst, const float* src) {
    asm volatile("cp.async.ca.shared.global [%0], [%1], 16;" :: "r"(dst), "l"(src));
}
__device__ __forceinline__ void cpa_commit() {
    asm volatile("cp.async.commit_group;" ::: "memory");
}
template <int N> __device__ __forceinline__ void cpa_wait() {
    asm volatile("cp.async.wait_group %0;" :: "n"(N) : "memory");
}

// ---------------------------------------------------------------------------
// Kernel 1: fused table + Hermite interp (unchanged from R7).
// ---------------------------------------------------------------------------
__global__ __launch_bounds__(256) void fused_cross(
    const float* __restrict__ visual, const float* __restrict__ tactile)
{
    __shared__ __align__(16) float vl[CH];
    __shared__ __align__(16) float vl2[CH];
    __shared__ float sden[G][8], snum[G][8], sm2[G][8];
    __shared__ float tab[G], der[G];

    const int b = blockIdx.x;
    const float LOG2E = 1.4426950408889634f;
    const float LN2   = 0.6931471805599453f;

    if (b == 0 && threadIdx.x < NTILES) g_cnt[threadIdx.x] = 0;

    const float* vb = visual + b * CH;
#pragma unroll
    for (int k = 0; k < 4; k++) {
        int idx = threadIdx.x + k * 256;
        float v = vb[idx] * LOG2E;
        vl[idx] = v;
        vl2[idx] = v * v;
    }
    __syncthreads();

    const int p  = threadIdx.x >> 3;
    const int h8 = threadIdx.x & 7;
    const float s = -GRANGE + GSTEP * (float)p;

    float den0 = 0.f, den1 = 0.f, num0 = 0.f, num1 = 0.f, m20 = 0.f, m21 = 0.f;
    const float4* v4 = reinterpret_cast<const float4*>(vl);
    const float4* w4 = reinterpret_cast<const float4*>(vl2);
#pragma unroll 4
    for (int j = 0; j < CH / 32; j++) {
        float4 v = v4[j * 8 + h8];
        float4 w = w4[j * 8 + h8];
        float e0 = ex2f(s * v.x);
        float e1 = ex2f(s * v.y);
        float e2 = ex2f(s * v.z);
        float e3 = ex2f(s * v.w);
        den0 += e0 + e2;
        den1 += e1 + e3;
        num0 = fmaf(e0, v.x, num0);
        num1 = fmaf(e1, v.y, num1);
        num0 = fmaf(e2, v.z, num0);
        num1 = fmaf(e3, v.w, num1);
        m20 = fmaf(e0, w.x, m20);
        m21 = fmaf(e1, w.y, m21);
        m20 = fmaf(e2, w.z, m20);
        m21 = fmaf(e3, w.w, m21);
    }
    sden[p][h8] = den0 + den1;
    snum[p][h8] = num0 + num1;
    sm2[p][h8]  = m20 + m21;
    __syncthreads();

    if (threadIdx.x < G) {
        int q = threadIdx.x;
        float den = 0.f, num = 0.f, m2 = 0.f;
#pragma unroll
        for (int r = 0; r < 8; r++) { den += sden[q][r]; num += snum[q][r]; m2 += sm2[q][r]; }
        float inv = __fdividef(1.0f, den);
        float nd = num * inv;
        tab[q] = nd * LN2;
        der[q] = (LN2 * LN2) * (m2 * inv - nd * nd) * GSTEP;
    }
    __syncthreads();

#pragma unroll
    for (int k = 0; k < 4; k++) {
        int i = threadIdx.x + k * 256;
        float t = tactile[b * CH + i];
        float x = (t + GRANGE) * (1.0f / GSTEP);
        x = fminf(fmaxf(x, 0.0f), (float)(G - 1) - 1e-3f);
        int i1 = (int)x;
        float u = x - (float)i1;
        float p1 = tab[i1], p2 = tab[i1 + 1];
        float m1 = der[i1], m2 = der[i1 + 1];
        float c2 = 3.0f * (p2 - p1) - 2.0f * m1 - m2;
        float c3 = 2.0f * (p1 - p2) + m1 + m2;
        float crossed = ((c3 * u + c2) * u + m1) * u + p1;
        g_h[b * CH + i] = vl[i] * LN2 + crossed;
        g_acc[b * CH + i] = 0.f;
    }
}

// ---------------------------------------------------------------------------
// Kernel 2: split-K GEMM + finalize, cp.async pipelined.
// grid = 16 n-tiles x 16 k-splits, 256 threads, 2 CTAs/SM.
// W gather: lanes -> consecutive k (9 lines/warp instead of 32). W smem [o][k]
// double-buffered; h smem [b][k] single-buffered (refill cost tiny).
// ---------------------------------------------------------------------------
__global__ __launch_bounds__(256, 2) void gemm_final(
    const float* __restrict__ conv_w,
    const float* __restrict__ cb, const float* __restrict__ gamma,
    const float* __restrict__ beta, const float* __restrict__ mean,
    const float* __restrict__ var, float* __restrict__ out)
{
    __shared__ __align__(16) float sh[BATCH * SHROW];          // 18.4 KB
    __shared__ __align__(16) float sw[2][G_NTILE * SWROW];     // 17.4 KB
    __shared__ float sA[G_NTILE], sC[G_NTILE];
    __shared__ int s_done;

    const int nb = blockIdx.x & (NTILES - 1);
    const int kz = blockIdx.x >> 4;
    const int nbase = nb * G_NTILE;
    const int kbase = kz * G_KCHUNK;

    const int t = threadIdx.x;
    const int tx = t & 15;             // o lane: o = tx + 16*oi
    const int ty = t >> 4;             // b lane: b = ty + 16*bi
    const int lane = t & 31;           // = k within W gather warp
    const int wrp  = t >> 5;

    const u32 sh_base = (u32)__cvta_generic_to_shared(sh);
    const u32 sw_base0 = (u32)__cvta_generic_to_shared(&sw[0][0]);
    const u32 sw_base1 = (u32)__cvta_generic_to_shared(&sw[1][0]);

    // ---- issue stage0: h + W ----
#pragma unroll
    for (int it = 0; it < 4; it++) {
        int e = t + it * 256;
        int r = e >> 3, c4 = (e & 7) * 4;
        cpa16(sh_base + (r * SHROW + c4) * 4, &g_h[r * CH + kbase + c4]);
    }
#pragma unroll
    for (int it = 0; it < 8; it++) {
        int o = wrp + 8 * it;          // lanes sweep k -> 9-line span per warp
        cpa4(sw_base0 + (o * SWROW + lane) * 4,
             &conv_w[((nbase + o) * CH + kbase + lane) * 9 + 4]);
    }
    cpa_commit();
    // ---- issue stage1 W (prefetch; latency hides behind compute0) ----
#pragma unroll
    for (int it = 0; it < 8; it++) {
        int o = wrp + 8 * it;
        cpa4(sw_base1 + (o * SWROW + lane) * 4,
             &conv_w[((nbase + o) * CH + kbase + KT + lane) * 9 + 4]);
    }
    cpa_commit();

    u64 acc[8][4] = {};

    cpa_wait<1>();                     // stage0 ready
    __syncthreads();

    // ---- compute stage 0 ----
#pragma unroll 4
    for (int kp = 0; kp < KT / 2; kp++) {
        u64 hb[8], wo[4];
#pragma unroll
        for (int bi = 0; bi < 8; bi++)
            hb[bi] = *(const u64*)&sh[(ty + 16 * bi) * SHROW + kp * 2];
#pragma unroll
        for (int oi = 0; oi < 4; oi++)
            wo[oi] = *(const u64*)&sw[0][(tx + 16 * oi) * SWROW + kp * 2];
#pragma unroll
        for (int bi = 0; bi < 8; bi++)
#pragma unroll
            for (int oi = 0; oi < 4; oi++)
                acc[bi][oi] = fma2(hb[bi], wo[oi], acc[bi][oi]);
    }
    __syncthreads();                   // done reading sh

    // ---- refill h for stage 1 ----
#pragma unroll
    for (int it = 0; it < 4; it++) {
        int e = t + it * 256;
        int r = e >> 3, c4 = (e & 7) * 4;
        cpa16(sh_base + (r * SHROW + c4) * 4, &g_h[r * CH + kbase + KT + c4]);
    }
    cpa_commit();
    cpa_wait<0>();                     // stage1 W + h ready
    __syncthreads();

    // ---- compute stage 1 ----
#pragma unroll 4
    for (int kp = 0; kp < KT / 2; kp++) {
        u64 hb[8], wo[4];
#pragma unroll
        for (int bi = 0; bi < 8; bi++)
            hb[bi] = *(const u64*)&sh[(ty + 16 * bi) * SHROW + kp * 2];
#pragma unroll
        for (int oi = 0; oi < 4; oi++)
            wo[oi] = *(const u64*)&sw[1][(tx + 16 * oi) * SWROW + kp * 2];
#pragma unroll
        for (int bi = 0; bi < 8; bi++)
#pragma unroll
            for (int oi = 0; oi < 4; oi++)
                acc[bi][oi] = fma2(hb[bi], wo[oi], acc[bi][oi]);
    }

    // ---- partial accumulate ----
#pragma unroll
    for (int bi = 0; bi < 8; bi++) {
        int b = ty + 16 * bi;
#pragma unroll
        for (int oi = 0; oi < 4; oi++) {
            float lo, hi; upkf(lo, hi, acc[bi][oi]);
            atomicAdd(&g_acc[b * CH + nbase + tx + 16 * oi], lo + hi);
        }
    }

    // ---- finalize: last k-split CTA per n-tile ----
    __threadfence();
    __syncthreads();
    if (t == 0) {
        unsigned int old = atomicAdd(&g_cnt[nb], 1u);
        s_done = (old == G_KSPLIT - 1) ? 1 : 0;
    }
    __syncthreads();
    if (!s_done) return;

    __threadfence();
    if (t < G_NTILE) {
        int o = nbase + t;
        float A = gamma[o] * rsqrtf(var[o] + 1e-5f);
        sA[t] = A;
        sC[t] = (cb[o] - mean[o]) * A + beta[o];
    }
    __syncthreads();

#pragma unroll
    for (int it = 0; it < 8; it++) {
        int e = t + it * 256;
        int b = e >> 4;
        int oq = (e & 15) * 4;
        int off = b * CH + nbase + oq;
        float4 sv = __ldcg((const float4*)&g_acc[off]);
        float4 r;
        float v;
        v = sv.x * sA[oq + 0] + sC[oq + 0]; r.x = v > 0.f ? v : 0.1f * v;
        v = sv.y * sA[oq + 1] + sC[oq + 1]; r.y = v > 0.f ? v : 0.1f * v;
        v = sv.z * sA[oq + 2] + sC[oq + 2]; r.z = v > 0.f ? v : 0.1f * v;
        v = sv.w * sA[oq + 3] + sC[oq + 3]; r.w = v > 0.f ? v : 0.1f * v;
        *(float4*)&out[off] = r;
    }
}

extern "C" void kernel_launch(void* const* d_in, const int* in_sizes, int n_in,
                              void* d_out, int out_size)
{
    const float* visual  = (const float*)d_in[0];
    const float* tactile = (const float*)d_in[1];
    const float* conv_w  = (const float*)d_in[2];
    const float* conv_b  = (const float*)d_in[3];
    const float* gamma   = (const float*)d_in[4];
    const float* beta    = (const float*)d_in[5];
    const float* mean    = (const float*)d_in[6];
    const float* var     = (const float*)d_in[7];
    float* out = (float*)d_out;

    fused_cross<<<BATCH, 256>>>(visual, tactile);
    gemm_final<<<NTILES * G_KSPLIT, 256>>>(conv_w, conv_b, gamma, beta, mean, var, out);
}